// round 1
// baseline (speedup 1.0000x reference)
#include <cuda_runtime.h>

// TPS_1279900254572
//
// Algebraic collapse: the reference solves  param = inv(L) @ Y  with
// Y = zeros((bs, gs, n+3, 2)).  inv(L) is finite (L is regularized with
// +0.01*I; K uses log(d^2 + 1e-9) which is finite for all d^2 >= 0), so
// param == 0 exactly, hence theta == 0 and control_params == 0, hence
// transformed == 0 and rbf == 0, hence the output is bit-exact zeros of
// shape (bs, h, w, 2).  The only required work is zero-filling d_out
// (which the harness poisons to 0xAA before timing).

__global__ void tps_zero_fill_kernel(float4* __restrict__ out, int n4) {
    int i = blockIdx.x * blockDim.x + threadIdx.x;
    if (i < n4) {
        out[i] = make_float4(0.0f, 0.0f, 0.0f, 0.0f);
    }
}

// Tail path in case out_size is not a multiple of 4 (shape variants).
__global__ void tps_zero_fill_tail_kernel(float* __restrict__ out,
                                          int start, int n) {
    int i = start + blockIdx.x * blockDim.x + threadIdx.x;
    if (i < n) {
        out[i] = 0.0f;
    }
}

extern "C" void kernel_launch(void* const* d_in, const int* in_sizes, int n_in,
                              void* d_out, int out_size) {
    (void)d_in; (void)in_sizes; (void)n_in;

    float* out = (float*)d_out;

    int n4 = out_size >> 2;          // number of float4 elements
    int rem_start = n4 << 2;         // first element of the scalar tail

    if (n4 > 0) {
        const int threads = 256;
        int blocks = (n4 + threads - 1) / threads;
        tps_zero_fill_kernel<<<blocks, threads>>>((float4*)out, n4);
    }
    if (rem_start < out_size) {
        int tail = out_size - rem_start;
        const int threads = 128;
        int blocks = (tail + threads - 1) / threads;
        tps_zero_fill_tail_kernel<<<blocks, threads>>>(out, rem_start, out_size);
    }
}

// round 3
// speedup vs baseline: 1.0350x; 1.0350x over previous
#include <cuda_runtime.h>

// TPS_1279900254572
//
// Algebraic collapse (verified in R1, rel_err == 0.0):
//   Y = zeros -> param = inv(L) @ Y == 0 exactly -> theta == 0,
//   control_params == 0 -> transformed == 0, rbf == 0 -> output is
//   bit-exact zeros of shape (bs, h, w, 2).
//
// R1 ncu: custom fill kernel was latency-bound (DRAM 0%, issue 10.7%,
// 3.9us for what is ~0.35us of L2 write traffic). Replace the kernel
// launch with a cudaMemsetAsync node: graph-capturable, allocation-free,
// and uses the driver's optimized fill path. fp32 0.0f is bitwise zero,
// so a byte memset of 0 is exact for any out_size.
//
// (R2 was a broker GPUAcquisitionTimeout — infra, not a kernel result.
//  Resubmitting unchanged.)

extern "C" void kernel_launch(void* const* d_in, const int* in_sizes, int n_in,
                              void* d_out, int out_size) {
    (void)d_in; (void)in_sizes; (void)n_in;
    cudaMemsetAsync(d_out, 0, (size_t)out_size * sizeof(float), 0);
}